// round 9
// baseline (speedup 1.0000x reference)
#include <cuda_runtime.h>
#include <cstdint>
#include <math.h>

#define NS    400000
#define NTHR  128
#define SPT   2
#define BROWS (NTHR * SPT)        // 256 samples per block
#define NBH   782                 // blocks per half launch: 782*256 = 200192
#define NB1   (2 * NBH)           // 1564 stat blocks total
#define NB3   391                 // k3 blocks (4 samples/thread, 256 thr)
#define NQ    41                  // 1 (loss1) + 4*10 GMM stats
#define NWARP (NTHR / 32)         // 4

// ---------------- device scratch (no allocations allowed) ----------------
__device__ float g_scratch[NB1 * 48];   // per-block stat partials
__device__ float g_z[3 * NS];           // z components, SoA (16B-aligned sections)
__device__ float g_params[48];          // per-k params + loss partial
__device__ float g_esum[NB3];           // per-block energy partials
__device__ int   g_cnt1 = 0;            // last-block ticket for k1b (self-resetting)
__device__ int   g_cnt3 = 0;            // last-block ticket for k3

typedef unsigned long long ull;

// ---------------- helpers ----------------
__device__ __forceinline__ ull pk2(float a, float b) {
    ull r; asm("mov.b64 %0, {%1, %2};" : "=l"(r) : "f"(a), "f"(b)); return r;
}
__device__ __forceinline__ void upk(ull v, float& a, float& b) {
    asm("mov.b64 {%0, %1}, %2;" : "=f"(a), "=f"(b) : "l"(v));
}
__device__ __forceinline__ void ffma2(ull& d, ull a, ull b) {
    asm("fma.rn.f32x2 %0, %1, %2, %0;" : "+l"(d) : "l"(a), "l"(b));
}
__device__ __forceinline__ float tanh_fast(float x) {
    float e = __expf(2.0f * x);
    return 1.0f - __fdividef(2.0f, e + 1.0f);
}
__device__ __forceinline__ float warp_sum(float v) {
#pragma unroll
    for (int o = 16; o > 0; o >>= 1) v += __shfl_down_sync(0xffffffffu, v, o);
    return v;
}
__device__ __forceinline__ double warp_dsum(double v) {
#pragma unroll
    for (int o = 16; o > 0; o >>= 1) v += __shfl_down_sync(0xffffffffu, v, o);
    return v;
}

// ---------------- K1: fused forward + stats, 2 samples/thread, 128thr/3blk ----------------
__global__ __launch_bounds__(NTHR, 3) void k1(
    const float* __restrict__ x1,
    const float* __restrict__ ew1, const float* __restrict__ eb1,
    const float* __restrict__ ew2, const float* __restrict__ eb2,
    const float* __restrict__ ew3, const float* __restrict__ eb3,
    const float* __restrict__ dw1, const float* __restrict__ db1,
    const float* __restrict__ dw2, const float* __restrict__ db2,
    const float* __restrict__ dw3, const float* __restrict__ db3,
    const float* __restrict__ tw1, const float* __restrict__ tb1,
    const float* __restrict__ tw2, const float* __restrict__ tb2,
    int blk_off, int do_final)
{
    __shared__ __align__(16) float sWc[4096];      // [128][32]: [enc_w1 | dec_w3^T]
    __shared__ float sX[NWARP * 1088];             // per-warp 64x17 staged x tile
    __shared__ __align__(16) float sM[256];        // dec_w3 @ dec_w3^T
    __shared__ __align__(16) float sB3[128];
    __shared__ float sV[16];
    __shared__ float sEB1[16], sEW2[128], sEB2[8], sEW3[8];
    __shared__ float sDW1[8], sDB1[8], sDW2[128], sDB2[16];
    __shared__ float sTW1[24], sTB1[8], sTW2[32], sTB2[4];
    __shared__ float sEB3, sBB;
    __shared__ float sWred[NQ][NWARP];
    __shared__ double sTot[NQ];
    __shared__ double sL3[4];
    __shared__ int sIsLast;

    const int tid = threadIdx.x;
    const int lane = tid & 31, wid = tid >> 5;

    // ---- load weights (fused layout built on the fly) ----
    for (int idx = tid; idx < 4096; idx += NTHR) {
        int i = idx >> 5, c = idx & 31;
        sWc[idx] = (c < 16) ? ew1[i * 16 + c] : dw3[(c - 16) * 128 + i];
    }
    if (tid < 128) { sB3[tid] = db3[tid]; sEW2[tid] = ew2[tid]; sDW2[tid] = dw2[tid]; }
    if (tid < 16)  { sEB1[tid] = eb1[tid]; sDB2[tid] = db2[tid]; }
    if (tid < 8)   { sEB2[tid] = eb2[tid]; sEW3[tid] = ew3[tid];
                     sDW1[tid] = dw1[tid]; sDB1[tid] = db1[tid]; sTB1[tid] = tb1[tid]; }
    if (tid < 24)  sTW1[tid] = tw1[tid];
    if (tid < 32)  sTW2[tid] = tw2[tid];
    if (tid < 4)   sTB2[tid] = tb2[tid];
    if (tid == 0)  sEB3 = eb3[0];
    __syncthreads();

    // ---- per-block decoder-algebra constants (cheap, from smem) ----
    for (int idx = tid; idx < 256; idx += NTHR) {
        int j = idx >> 4, l = idx & 15;
        float s = 0.0f;
#pragma unroll 8
        for (int i = 0; i < 128; i++)
            s += sWc[i * 32 + 16 + j] * sWc[i * 32 + 16 + l];
        sM[idx] = s;
    }
    if (tid < 16) {
        float s = 0.0f;
#pragma unroll 8
        for (int i = 0; i < 128; i++) s += sWc[i * 32 + 16 + tid] * sB3[i];
        sV[tid] = s;
    }
    if (tid == 16) {
        float s = 0.0f;
#pragma unroll 8
        for (int i = 0; i < 128; i++) s += sB3[i] * sB3[i];
        sBB = s;
    }
    __syncthreads();

    const int gbid = blockIdx.x + blk_off;
    const int rowbase = gbid * BROWS;
    const int nA = rowbase + tid;
    const int nB = rowbase + NTHR + tid;
    const float vA = (nA < NS) ? 1.0f : 0.0f;
    const float vB = (nB < NS) ? 1.0f : 0.0f;

    float* const sXw = sX + wid * 1088;
    const float* const xrA = sXw + lane * 17;
    const float* const xrB = sXw + (32 + lane) * 17;
    const int r0 = lane >> 2, ch = lane & 3;

    // ---- fused 128->32 matvec for 2 samples: warp-private tiles, syncwarp only ----
    ull A[16], B[16];
#pragma unroll
    for (int q = 0; q < 16; q++) { A[q] = 0ull; B[q] = 0ull; }
    ull accN = 0ull, accB3 = 0ull;    // packed (A,B) accumulators for n1sq, x.b3

#pragma unroll 1
    for (int t = 0; t < 8; t++) {
        // stage 64 rows x 16 cols for this warp (samples A rows then B rows)
#pragma unroll
        for (int j = 0; j < 4; j++) {
            int row = r0 + j * 8;
            int rgA = rowbase + wid * 32 + row;          if (rgA >= NS) rgA = NS - 1;
            int rgB = rowbase + NTHR + wid * 32 + row;   if (rgB >= NS) rgB = NS - 1;
            const float4 va = *(const float4*)(x1 + (size_t)rgA * 128 + t * 16 + ch * 4);
            const float4 vb = *(const float4*)(x1 + (size_t)rgB * 128 + t * 16 + ch * 4);
            float* dA = sXw + row * 17 + ch * 4;
            float* dB = sXw + (32 + row) * 17 + ch * 4;
            dA[0] = va.x; dA[1] = va.y; dA[2] = va.z; dA[3] = va.w;
            dB[0] = vb.x; dB[1] = vb.y; dB[2] = vb.z; dB[3] = vb.w;
        }
        __syncwarp();
#pragma unroll
        for (int c = 0; c < 16; c++) {
            const float xa = xrA[c];
            const float xb = xrB[c];
            const int gc = t * 16 + c;
            const float b3c = sB3[gc];
            const ull pab = pk2(xa, xb);
            ffma2(accN, pab, pab);
            ffma2(accB3, pab, pk2(b3c, b3c));
            const ull pa = pk2(xa, xa);
            const ull pb = pk2(xb, xb);
            const ulonglong2* w = (const ulonglong2*)(sWc + gc * 32);
#pragma unroll
            for (int q = 0; q < 8; q++) {
                ulonglong2 tw = w[q];
                ffma2(A[2 * q],     pa, tw.x);
                ffma2(A[2 * q + 1], pa, tw.y);
                ffma2(B[2 * q],     pb, tw.x);
                ffma2(B[2 * q + 1], pb, tw.y);
            }
        }
        __syncwarp();   // protect sXw before next stage overwrites
    }
    float n1A, n1B, xb3A, xb3B;
    upk(accN, n1A, n1B);
    upk(accB3, xb3A, xb3B);

    // ---- per-sample tail (inlined twice via lambda on register arrays) ----
    float fA[3], fB[3], gmA[4], gmB[4], dsvA, dsvB;

    auto tail = [&](ull (&U)[16], float n1sq, float xb3, int n, float valid,
                    float (&f)[3], float (&gm)[4], float& dsv) {
        // encoder layer 1 straight from packed accumulators (U[0..7])
        float h1[16];
#pragma unroll
        for (int q = 0; q < 8; q++) {
            float a, b;
            upk(U[q], a, b);
            h1[2 * q]     = tanh_fast(a + sEB1[2 * q]);
            h1[2 * q + 1] = tanh_fast(b + sEB1[2 * q + 1]);
        }
        float h2[8];
#pragma unroll
        for (int o = 0; o < 8; o++) {
            float sm = sEB2[o];
#pragma unroll
            for (int i = 0; i < 16; i++) sm += h1[i] * sEW2[i * 8 + o];
            h2[o] = tanh_fast(sm);
        }
        float s3 = sEB3;
#pragma unroll
        for (int i = 0; i < 8; i++) s3 += h2[i] * sEW3[i];
        const float zc0 = tanh_fast(s3);

        float g1[8];
#pragma unroll
        for (int o = 0; o < 8; o++) g1[o] = tanh_fast(sDB1[o] + zc0 * sDW1[o]);
        float g2[16];
        ull gp[8];
#pragma unroll
        for (int o = 0; o < 16; o++) {
            float sm = sDB2[o];
#pragma unroll
            for (int i = 0; i < 8; i++) sm += g1[i] * sDW2[i * 16 + o];
            g2[o] = tanh_fast(sm);
        }
#pragma unroll
        for (int q = 0; q < 8; q++) gp[q] = pk2(g2[2 * q], g2[2 * q + 1]);

        // dot(x1,x2) via packed t16 in U[8..15]
        ull accd = 0ull;
#pragma unroll
        for (int q = 0; q < 8; q++) ffma2(accd, gp[q], U[8 + q]);
        float da, db2; upk(accd, da, db2);
        float dotv = xb3 + da + db2;

        float n2sq = sBB;
#pragma unroll
        for (int j = 0; j < 16; j++) {
            ull acc = pk2(2.0f * sV[j], 0.0f);
            const ulonglong2* Mr = (const ulonglong2*)(sM + j * 16);
#pragma unroll
            for (int q = 0; q < 4; q++) {
                ulonglong2 m = Mr[q];
                ffma2(acc, gp[2 * q],     m.x);
                ffma2(acc, gp[2 * q + 1], m.y);
            }
            float pa, pb; upk(acc, pa, pb);
            n2sq += g2[j] * (pa + pb);
        }
        const float dsq = fmaxf(n1sq - 2.0f * dotv + n2sq, 0.0f);
        const float zc1 = dotv * rsqrtf(n1sq * n2sq);
        const float zc2 = sqrtf(dsq);

        if (n < NS) {
            g_z[n]          = zc0;
            g_z[NS + n]     = zc1;
            g_z[2 * NS + n] = zc2;
        }

        float tt[8];
#pragma unroll
        for (int o = 0; o < 8; o++)
            tt[o] = tanh_fast(sTB1[o] + zc0 * sTW1[o] + zc1 * sTW1[8 + o] + zc2 * sTW1[16 + o]);
        float lg[4];
#pragma unroll
        for (int k = 0; k < 4; k++) {
            float sm = sTB2[k];
#pragma unroll
            for (int o = 0; o < 8; o++) sm += tt[o] * sTW2[o * 4 + k];
            lg[k] = sm;
        }
        float m = fmaxf(fmaxf(lg[0], lg[1]), fmaxf(lg[2], lg[3]));
        float e0 = __expf(lg[0] - m), e1 = __expf(lg[1] - m);
        float e2 = __expf(lg[2] - m), e3 = __expf(lg[3] - m);
        float inv = __fdividef(1.0f, e0 + e1 + e2 + e3) * valid;
        f[0] = zc0; f[1] = zc1; f[2] = zc2;
        gm[0] = e0 * inv; gm[1] = e1 * inv; gm[2] = e2 * inv; gm[3] = e3 * inv;
        dsv = dsq * valid;
    };

    tail(A, n1A, xb3A, nA, vA, fA, gmA, dsvA);
    tail(B, n1B, xb3B, nB, vB, fB, gmB, dsvB);

    // ---- deterministic block reduction of 41 statistics (both samples fused) ----
    {
        float s = warp_sum(dsvA + dsvB);
        if (lane == 0) sWred[0][wid] = s;
    }
#pragma unroll
    for (int k = 0; k < 4; k++) {
        float vv[10];
        vv[0] = gmA[k] + gmB[k];
#pragma unroll
        for (int d = 0; d < 3; d++) vv[1 + d] = gmA[k] * fA[d] + gmB[k] * fB[d];
        int c = 4;
#pragma unroll
        for (int d = 0; d < 3; d++)
#pragma unroll
            for (int e = d; e < 3; e++)
                vv[c++] = gmA[k] * fA[d] * fA[e] + gmB[k] * fB[d] * fB[e];
#pragma unroll
        for (int q = 0; q < 10; q++) {
            float s = warp_sum(vv[q]);
            if (lane == 0) sWred[1 + k * 10 + q][wid] = s;
        }
    }
    __syncthreads();
    if (tid < NQ) {
        float s = 0.0f;
#pragma unroll
        for (int w = 0; w < NWARP; w++) s += sWred[tid][w];
        g_scratch[gbid * 48 + tid] = s;
    }

    if (!do_final) return;

    // ---- last block of second launch: global reduce + GMM params ----
    __threadfence();
    __syncthreads();
    if (tid == 0) sIsLast = (atomicAdd(&g_cnt1, 1) == NBH - 1);
    __syncthreads();
    if (!sIsLast) return;
    __threadfence();

    for (int q = wid; q < NQ; q += NWARP) {
        double s = 0.0;
        for (int b = lane; b < NB1; b += 32) s += (double)g_scratch[b * 48 + q];
        s = warp_dsum(s);
        if (lane == 0) sTot[q] = s;
    }
    __syncthreads();
    if (tid < 4) {
        const int k = tid;
        const double* T = sTot + 1 + k * 10;
        double S0 = T[0];
        double m0 = T[1] / S0, m1 = T[2] / S0, m2 = T[3] / S0;
        double s00 = T[4] / S0 - m0 * m0, s01 = T[5] / S0 - m0 * m1, s02 = T[6] / S0 - m0 * m2;
        double s11 = T[7] / S0 - m1 * m1, s12 = T[8] / S0 - m1 * m2, s22 = T[9] / S0 - m2 * m2;
        double c00 = s11 * s22 - s12 * s12;
        double c01 = s02 * s12 - s01 * s22;
        double c02 = s01 * s12 - s02 * s11;
        double det = s00 * c00 + s01 * c01 + s02 * c02;
        double inv = 1.0 / det;
        double phi = S0 / (double)NS;
        double ck = log(phi) - 0.5 * (3.0 * log(2.0 * M_PI) + log(det));
        g_params[k * 10 + 0] = (float)m0;
        g_params[k * 10 + 1] = (float)m1;
        g_params[k * 10 + 2] = (float)m2;
        g_params[k * 10 + 3] = (float)(c00 * inv);
        g_params[k * 10 + 4] = (float)(c01 * inv);
        g_params[k * 10 + 5] = (float)(c02 * inv);
        g_params[k * 10 + 6] = (float)((s00 * s22 - s02 * s02) * inv);
        g_params[k * 10 + 7] = (float)((s02 * s01 - s00 * s12) * inv);
        g_params[k * 10 + 8] = (float)((s00 * s11 - s01 * s01) * inv);
        g_params[k * 10 + 9] = (float)ck;
        sL3[k] = 1.0 / s00 + 1.0 / s11 + 1.0 / s22;
    }
    __syncthreads();
    if (tid == 0) {
        double loss1 = sTot[0] / (double)NS;
        g_params[40] = (float)(loss1 + 1e-4 * (sL3[0] + sL3[1] + sL3[2] + sL3[3]));
        __threadfence();
        g_cnt1 = 0;                 // self-reset for next graph replay
    }
}

// ---------------- K3: energy, 4 samples/thread + (last block) final loss ----------------
__global__ __launch_bounds__(256) void k3(float* __restrict__ out, int out_size) {
    __shared__ float p[48];
    __shared__ float sw[8];
    __shared__ int sIsLast;
    const int tid = threadIdx.x;
    const int lane = tid & 31, wid = tid >> 5;
    if (tid < 41) p[tid] = g_params[tid];
    __syncthreads();

    const int i4 = blockIdx.x * 256 + tid;      // float4 index; NS/4 = 100000 exact
    float esum = 0.0f;
    if (i4 < NS / 4) {
        const float4 z0 = ((const float4*)g_z)[i4];
        const float4 z1 = ((const float4*)(g_z + NS))[i4];
        const float4 z2 = ((const float4*)(g_z + 2 * NS))[i4];
        const float a0[4] = {z0.x, z0.y, z0.z, z0.w};
        const float a1[4] = {z1.x, z1.y, z1.z, z1.w};
        const float a2[4] = {z2.x, z2.y, z2.z, z2.w};
        float e4[4];
#pragma unroll
        for (int s = 0; s < 4; s++) {
            float e = 0.0f;
#pragma unroll
            for (int k = 0; k < 4; k++) {
                const float* P = p + k * 10;
                float v0 = a0[s] - P[0], v1 = a1[s] - P[1], v2 = a2[s] - P[2];
                float q = v0 * v0 * P[3] + v1 * v1 * P[6] + v2 * v2 * P[8]
                        + 2.0f * (v0 * v1 * P[4] + v0 * v2 * P[5] + v1 * v2 * P[7]);
                e += 0.5f * q - P[9];
            }
            e4[s] = e;
            esum += e;
        }
        float4 ov; ov.x = e4[0]; ov.y = e4[1]; ov.z = e4[2]; ov.w = e4[3];
        ((float4*)out)[i4] = ov;
    }

    float s = warp_sum(esum);
    if (lane == 0) sw[wid] = s;
    __syncthreads();
    if (tid == 0) {
        float t = 0.0f;
#pragma unroll
        for (int w = 0; w < 8; w++) t += sw[w];
        g_esum[blockIdx.x] = t;
    }
    __threadfence();
    __syncthreads();
    if (tid == 0) sIsLast = (atomicAdd(&g_cnt3, 1) == NB3 - 1);
    __syncthreads();
    if (!sIsLast) return;
    __threadfence();
    if (wid == 0) {
        double a = 0.0;
        for (int b = lane; b < NB3; b += 32) a += (double)g_esum[b];
        a = warp_dsum(a);
        if (lane == 0) {
            if (out_size > NS)
                out[NS] = p[40] + (float)(0.01 * (a / (double)NS));
            __threadfence();
            g_cnt3 = 0;             // self-reset for next graph replay
        }
    }
}

extern "C" void kernel_launch(void* const* d_in, const int* in_sizes, int n_in,
                              void* d_out, int out_size) {
    const float* x1  = (const float*)d_in[0];
    const float* ew1 = (const float*)d_in[1];
    const float* eb1 = (const float*)d_in[2];
    const float* ew2 = (const float*)d_in[3];
    const float* eb2 = (const float*)d_in[4];
    const float* ew3 = (const float*)d_in[5];
    const float* eb3 = (const float*)d_in[6];
    const float* dw1 = (const float*)d_in[7];
    const float* db1 = (const float*)d_in[8];
    const float* dw2 = (const float*)d_in[9];
    const float* db2 = (const float*)d_in[10];
    const float* dw3 = (const float*)d_in[11];
    const float* db3 = (const float*)d_in[12];
    const float* tw1 = (const float*)d_in[13];
    const float* tb1 = (const float*)d_in[14];
    const float* tw2 = (const float*)d_in[15];
    const float* tb2 = (const float*)d_in[16];
    float* out = (float*)d_out;

    k1<<<NBH, NTHR>>>(x1, ew1, eb1, ew2, eb2, ew3, eb3,
                      dw1, db1, dw2, db2, dw3, db3,
                      tw1, tb1, tw2, tb2, 0, 0);
    k1<<<NBH, NTHR>>>(x1, ew1, eb1, ew2, eb2, ew3, eb3,
                      dw1, db1, dw2, db2, dw3, db3,
                      tw1, tb1, tw2, tb2, NBH, 1);
    k3<<<NB3, 256>>>(out, out_size);
}

// round 10
// speedup vs baseline: 1.9833x; 1.9833x over previous
#include <cuda_runtime.h>
#include <cstdint>
#include <math.h>

#define NS    400000
#define NTHR  256
#define SPT   2
#define BROWS (NTHR * SPT)        // 512 samples per kA block
#define NBA   782                 // kA blocks: 782*512 = 400384
#define NBB   1563                // kB blocks: 1563*256 = 400128
#define NB3   391                 // k3 blocks (4 samples/thread)
#define NQ    41                  // 1 (loss1) + 4*10 GMM stats

// ---------------- device scratch (no allocations allowed) ----------------
__device__ float4 g_mid4[8 * NS];       // [q][n]: q=0..3 enc16, q=4..7 t16
__device__ float2 g_misc[NS];           // (n1sq, x.b3)
__device__ float  g_M[256];             // dec_w3 @ dec_w3^T
__device__ float  g_V[16];              // dec_w3 @ dec_b3
__device__ float  g_BB[1];              // ||dec_b3||^2
__device__ float  g_scratch[NBB * 48];  // per-block stat partials
__device__ float  g_z[3 * NS];          // z components, SoA
__device__ float  g_params[48];         // per-k params + loss partial
__device__ float  g_esum[NB3];          // per-block energy partials
__device__ int    g_cntB = 0;           // last-block ticket for kB (self-resetting)
__device__ int    g_cnt3 = 0;           // last-block ticket for k3

typedef unsigned long long ull;

// ---------------- helpers ----------------
__device__ __forceinline__ ull pk2(float a, float b) {
    ull r; asm("mov.b64 %0, {%1, %2};" : "=l"(r) : "f"(a), "f"(b)); return r;
}
__device__ __forceinline__ void upk(ull v, float& a, float& b) {
    asm("mov.b64 {%0, %1}, %2;" : "=f"(a), "=f"(b) : "l"(v));
}
__device__ __forceinline__ void ffma2(ull& d, ull a, ull b) {
    asm("fma.rn.f32x2 %0, %1, %2, %0;" : "+l"(d) : "l"(a), "l"(b));
}
__device__ __forceinline__ float tanh_fast(float x) {
    float e = __expf(2.0f * x);
    return 1.0f - __fdividef(2.0f, e + 1.0f);
}
__device__ __forceinline__ float warp_sum(float v) {
#pragma unroll
    for (int o = 16; o > 0; o >>= 1) v += __shfl_down_sync(0xffffffffu, v, o);
    return v;
}
__device__ __forceinline__ double warp_dsum(double v) {
#pragma unroll
    for (int o = 16; o > 0; o >>= 1) v += __shfl_down_sync(0xffffffffu, v, o);
    return v;
}

// ---------------- K0: decoder-algebra constants (once) ----------------
__global__ void k0(const float* __restrict__ dw3, const float* __restrict__ db3) {
    __shared__ float sW[2048], sB[128];
    const int tid = threadIdx.x;   // 256
    for (int i = tid; i < 2048; i += 256) sW[i] = dw3[i];
    if (tid < 128) sB[tid] = db3[tid];
    __syncthreads();
    {
        int j = tid >> 4, l = tid & 15;
        float s = 0.0f;
#pragma unroll 8
        for (int i = 0; i < 128; i++) s += sW[j * 128 + i] * sW[l * 128 + i];
        g_M[tid] = s;
    }
    if (tid < 16) {
        float s = 0.0f;
#pragma unroll 8
        for (int i = 0; i < 128; i++) s += sW[tid * 128 + i] * sB[i];
        g_V[tid] = s;
    }
    if (tid == 16) {
        float s = 0.0f;
#pragma unroll 8
        for (int i = 0; i < 128; i++) s += sB[i] * sB[i];
        g_BB[0] = s;
    }
}

// ---------------- KA: 128->32 fused matvec, 2 samples/thread, matvec ONLY ----------------
__global__ __launch_bounds__(NTHR, 2) void kA(
    const float* __restrict__ x1,
    const float* __restrict__ ew1,
    const float* __restrict__ dw3,
    const float* __restrict__ db3)
{
    __shared__ __align__(16) float sWc[4096];      // [128][32]: [enc_w1 | dec_w3^T]
    __shared__ float sX[8 * 1088];                 // per-warp 64x17 staged x tile
    __shared__ __align__(16) float sB3[128];

    const int tid = threadIdx.x;
    const int lane = tid & 31, wid = tid >> 5;

    for (int idx = tid; idx < 4096; idx += NTHR) {
        int i = idx >> 5, c = idx & 31;
        sWc[idx] = (c < 16) ? ew1[i * 16 + c] : dw3[(c - 16) * 128 + i];
    }
    if (tid < 128) sB3[tid] = db3[tid];
    __syncthreads();

    const int rowbase = blockIdx.x * BROWS;
    const int nA = rowbase + tid;
    const int nB = rowbase + NTHR + tid;

    float* const sXw = sX + wid * 1088;
    const float* const xrA = sXw + lane * 17;
    const float* const xrB = sXw + (32 + lane) * 17;
    const int r0 = lane >> 2, ch = lane & 3;

    ull A[16], B[16];
#pragma unroll
    for (int q = 0; q < 16; q++) { A[q] = 0ull; B[q] = 0ull; }
    ull accN = 0ull, accB3 = 0ull;

#pragma unroll 1
    for (int t = 0; t < 8; t++) {
#pragma unroll
        for (int j = 0; j < 4; j++) {
            int row = r0 + j * 8;
            int rgA = rowbase + wid * 32 + row;          if (rgA >= NS) rgA = NS - 1;
            int rgB = rowbase + NTHR + wid * 32 + row;   if (rgB >= NS) rgB = NS - 1;
            const float4 va = *(const float4*)(x1 + (size_t)rgA * 128 + t * 16 + ch * 4);
            const float4 vb = *(const float4*)(x1 + (size_t)rgB * 128 + t * 16 + ch * 4);
            float* dA = sXw + row * 17 + ch * 4;
            float* dB = sXw + (32 + row) * 17 + ch * 4;
            dA[0] = va.x; dA[1] = va.y; dA[2] = va.z; dA[3] = va.w;
            dB[0] = vb.x; dB[1] = vb.y; dB[2] = vb.z; dB[3] = vb.w;
        }
        __syncwarp();
#pragma unroll
        for (int c = 0; c < 16; c++) {
            const float xa = xrA[c];
            const float xb = xrB[c];
            const int gc = t * 16 + c;
            const float b3c = sB3[gc];
            const ull pab = pk2(xa, xb);
            ffma2(accN, pab, pab);
            ffma2(accB3, pab, pk2(b3c, b3c));
            const ull pa = pk2(xa, xa);
            const ull pb = pk2(xb, xb);
            const ulonglong2* w = (const ulonglong2*)(sWc + gc * 32);
#pragma unroll
            for (int q = 0; q < 8; q++) {
                ulonglong2 tw = w[q];
                ffma2(A[2 * q],     pa, tw.x);
                ffma2(A[2 * q + 1], pa, tw.y);
                ffma2(B[2 * q],     pb, tw.x);
                ffma2(B[2 * q + 1], pb, tw.y);
            }
        }
        __syncwarp();
    }
    float n1A, n1B, xb3A, xb3B;
    upk(accN, n1A, n1B);
    upk(accB3, xb3A, xb3B);

    if (nA < NS) {
#pragma unroll
        for (int q = 0; q < 4; q++) {
            float a0, a1, a2, a3;
            upk(A[2 * q], a0, a1); upk(A[2 * q + 1], a2, a3);
            g_mid4[q * NS + nA] = make_float4(a0, a1, a2, a3);
            float b0, b1, b2, b3;
            upk(A[8 + 2 * q], b0, b1); upk(A[9 + 2 * q], b2, b3);
            g_mid4[(4 + q) * NS + nA] = make_float4(b0, b1, b2, b3);
        }
        g_misc[nA] = make_float2(n1A, xb3A);
    }
    if (nB < NS) {
#pragma unroll
        for (int q = 0; q < 4; q++) {
            float a0, a1, a2, a3;
            upk(B[2 * q], a0, a1); upk(B[2 * q + 1], a2, a3);
            g_mid4[q * NS + nB] = make_float4(a0, a1, a2, a3);
            float b0, b1, b2, b3;
            upk(B[8 + 2 * q], b0, b1); upk(B[9 + 2 * q], b2, b3);
            g_mid4[(4 + q) * NS + nB] = make_float4(b0, b1, b2, b3);
        }
        g_misc[nB] = make_float2(n1B, xb3B);
    }
}

// ---------------- KB: per-sample tail + stats + (last block) GMM params ----------------
__global__ __launch_bounds__(NTHR) void kB(
    const float* __restrict__ eb1,
    const float* __restrict__ ew2, const float* __restrict__ eb2,
    const float* __restrict__ ew3, const float* __restrict__ eb3,
    const float* __restrict__ dw1, const float* __restrict__ db1,
    const float* __restrict__ dw2, const float* __restrict__ db2,
    const float* __restrict__ tw1, const float* __restrict__ tb1,
    const float* __restrict__ tw2, const float* __restrict__ tb2)
{
    __shared__ __align__(16) float sM[256];
    __shared__ float sV[16];
    __shared__ float sEB1[16], sEW2[128], sEB2[8], sEW3[8];
    __shared__ float sDW1[8], sDB1[8], sDW2[128], sDB2[16];
    __shared__ float sTW1[24], sTB1[8], sTW2[32], sTB2[4];
    __shared__ float sEB3, sBB;
    __shared__ float sWred[NQ][8];
    __shared__ double sTot[NQ];
    __shared__ double sL3[4];
    __shared__ int sIsLast;

    const int tid = threadIdx.x;
    const int lane = tid & 31, wid = tid >> 5;

    if (tid < 256) sM[tid] = g_M[tid];
    if (tid < 128) { sEW2[tid] = ew2[tid]; sDW2[tid] = dw2[tid]; }
    if (tid < 16)  { sEB1[tid] = eb1[tid]; sDB2[tid] = db2[tid]; sV[tid] = g_V[tid]; }
    if (tid < 8)   { sEB2[tid] = eb2[tid]; sEW3[tid] = ew3[tid];
                     sDW1[tid] = dw1[tid]; sDB1[tid] = db1[tid]; sTB1[tid] = tb1[tid]; }
    if (tid < 24)  sTW1[tid] = tw1[tid];
    if (tid < 32)  sTW2[tid] = tw2[tid];
    if (tid < 4)   sTB2[tid] = tb2[tid];
    if (tid == 0)  { sEB3 = eb3[0]; sBB = g_BB[0]; }
    __syncthreads();

    const int n = blockIdx.x * NTHR + tid;
    const int ns = (n < NS) ? n : (NS - 1);
    const float valid = (n < NS) ? 1.0f : 0.0f;

    // ---- load intermediates ----
    float enc[16], t16[16];
#pragma unroll
    for (int q = 0; q < 4; q++) {
        const float4 e = g_mid4[q * NS + ns];
        enc[4 * q] = e.x; enc[4 * q + 1] = e.y; enc[4 * q + 2] = e.z; enc[4 * q + 3] = e.w;
        const float4 t = g_mid4[(4 + q) * NS + ns];
        t16[4 * q] = t.x; t16[4 * q + 1] = t.y; t16[4 * q + 2] = t.z; t16[4 * q + 3] = t.w;
    }
    const float2 mi = g_misc[ns];
    const float n1sq = mi.x, xb3 = mi.y;

    // ---- encoder ----
    float h1[16];
#pragma unroll
    for (int j = 0; j < 16; j++) h1[j] = tanh_fast(enc[j] + sEB1[j]);
    float h2[8];
#pragma unroll
    for (int o = 0; o < 8; o++) {
        float sm = sEB2[o];
#pragma unroll
        for (int i = 0; i < 16; i++) sm += h1[i] * sEW2[i * 8 + o];
        h2[o] = tanh_fast(sm);
    }
    float s3 = sEB3;
#pragma unroll
    for (int i = 0; i < 8; i++) s3 += h2[i] * sEW3[i];
    const float zc0 = tanh_fast(s3);

    // ---- decoder hidden ----
    float g1[8];
#pragma unroll
    for (int o = 0; o < 8; o++) g1[o] = tanh_fast(sDB1[o] + zc0 * sDW1[o]);
    float g2[16];
    ull gp[8];
#pragma unroll
    for (int o = 0; o < 16; o++) {
        float sm = sDB2[o];
#pragma unroll
        for (int i = 0; i < 8; i++) sm += g1[i] * sDW2[i * 16 + o];
        g2[o] = tanh_fast(sm);
    }
#pragma unroll
    for (int q = 0; q < 8; q++) gp[q] = pk2(g2[2 * q], g2[2 * q + 1]);

    // ---- distances via precomputed algebra ----
    float dotv = xb3;
#pragma unroll
    for (int j = 0; j < 16; j++) dotv += g2[j] * t16[j];
    float n2sq = sBB;
#pragma unroll
    for (int j = 0; j < 16; j++) {
        ull acc = pk2(2.0f * sV[j], 0.0f);
        const ulonglong2* Mr = (const ulonglong2*)(sM + j * 16);
#pragma unroll
        for (int q = 0; q < 4; q++) {
            ulonglong2 m = Mr[q];
            ffma2(acc, gp[2 * q],     m.x);
            ffma2(acc, gp[2 * q + 1], m.y);
        }
        float pa, pb; upk(acc, pa, pb);
        n2sq += g2[j] * (pa + pb);
    }
    const float dsq = fmaxf(n1sq - 2.0f * dotv + n2sq, 0.0f);
    const float zc1 = dotv * rsqrtf(n1sq * n2sq);
    const float zc2 = sqrtf(dsq);

    if (n < NS) {
        g_z[n]          = zc0;
        g_z[NS + n]     = zc1;
        g_z[2 * NS + n] = zc2;
    }

    // ---- estimator + softmax ----
    float gm[4];
    {
        float tt[8];
#pragma unroll
        for (int o = 0; o < 8; o++)
            tt[o] = tanh_fast(sTB1[o] + zc0 * sTW1[o] + zc1 * sTW1[8 + o] + zc2 * sTW1[16 + o]);
        float lg[4];
#pragma unroll
        for (int k = 0; k < 4; k++) {
            float sm = sTB2[k];
#pragma unroll
            for (int o = 0; o < 8; o++) sm += tt[o] * sTW2[o * 4 + k];
            lg[k] = sm;
        }
        float m = fmaxf(fmaxf(lg[0], lg[1]), fmaxf(lg[2], lg[3]));
        float e0 = __expf(lg[0] - m), e1 = __expf(lg[1] - m);
        float e2 = __expf(lg[2] - m), e3 = __expf(lg[3] - m);
        float inv = __fdividef(1.0f, e0 + e1 + e2 + e3) * valid;
        gm[0] = e0 * inv; gm[1] = e1 * inv; gm[2] = e2 * inv; gm[3] = e3 * inv;
    }
    const float dsv = dsq * valid;
    const float f[3] = {zc0, zc1, zc2};

    // ---- deterministic block reduction of 41 statistics ----
    {
        float s = warp_sum(dsv);
        if (lane == 0) sWred[0][wid] = s;
    }
#pragma unroll
    for (int k = 0; k < 4; k++) {
        float vv[10];
        vv[0] = gm[k];
#pragma unroll
        for (int d = 0; d < 3; d++) vv[1 + d] = gm[k] * f[d];
        int c = 4;
#pragma unroll
        for (int d = 0; d < 3; d++)
#pragma unroll
            for (int e = d; e < 3; e++) vv[c++] = gm[k] * f[d] * f[e];
#pragma unroll
        for (int q = 0; q < 10; q++) {
            float s = warp_sum(vv[q]);
            if (lane == 0) sWred[1 + k * 10 + q][wid] = s;
        }
    }
    __syncthreads();
    if (tid < NQ) {
        float s = 0.0f;
#pragma unroll
        for (int w = 0; w < 8; w++) s += sWred[tid][w];
        g_scratch[blockIdx.x * 48 + tid] = s;
    }

    // ---- last-block global reduce + GMM params (deterministic fixed order) ----
    __threadfence();
    __syncthreads();
    if (tid == 0) sIsLast = (atomicAdd(&g_cntB, 1) == NBB - 1);
    __syncthreads();
    if (!sIsLast) return;
    __threadfence();

    for (int q = wid; q < NQ; q += 8) {
        double s = 0.0;
        for (int b = lane; b < NBB; b += 32) s += (double)g_scratch[b * 48 + q];
        s = warp_dsum(s);
        if (lane == 0) sTot[q] = s;
    }
    __syncthreads();
    if (tid < 4) {
        const int k = tid;
        const double* T = sTot + 1 + k * 10;
        double S0 = T[0];
        double m0 = T[1] / S0, m1 = T[2] / S0, m2 = T[3] / S0;
        double s00 = T[4] / S0 - m0 * m0, s01 = T[5] / S0 - m0 * m1, s02 = T[6] / S0 - m0 * m2;
        double s11 = T[7] / S0 - m1 * m1, s12 = T[8] / S0 - m1 * m2, s22 = T[9] / S0 - m2 * m2;
        double c00 = s11 * s22 - s12 * s12;
        double c01 = s02 * s12 - s01 * s22;
        double c02 = s01 * s12 - s02 * s11;
        double det = s00 * c00 + s01 * c01 + s02 * c02;
        double inv = 1.0 / det;
        double phi = S0 / (double)NS;
        double ck = log(phi) - 0.5 * (3.0 * log(2.0 * M_PI) + log(det));
        g_params[k * 10 + 0] = (float)m0;
        g_params[k * 10 + 1] = (float)m1;
        g_params[k * 10 + 2] = (float)m2;
        g_params[k * 10 + 3] = (float)(c00 * inv);
        g_params[k * 10 + 4] = (float)(c01 * inv);
        g_params[k * 10 + 5] = (float)(c02 * inv);
        g_params[k * 10 + 6] = (float)((s00 * s22 - s02 * s02) * inv);
        g_params[k * 10 + 7] = (float)((s02 * s01 - s00 * s12) * inv);
        g_params[k * 10 + 8] = (float)((s00 * s11 - s01 * s01) * inv);
        g_params[k * 10 + 9] = (float)ck;
        sL3[k] = 1.0 / s00 + 1.0 / s11 + 1.0 / s22;
    }
    __syncthreads();
    if (tid == 0) {
        double loss1 = sTot[0] / (double)NS;
        g_params[40] = (float)(loss1 + 1e-4 * (sL3[0] + sL3[1] + sL3[2] + sL3[3]));
        __threadfence();
        g_cntB = 0;                 // self-reset for next graph replay
    }
}

// ---------------- K3: energy, 4 samples/thread + (last block) final loss ----------------
__global__ __launch_bounds__(256) void k3(float* __restrict__ out, int out_size) {
    __shared__ float p[48];
    __shared__ float sw[8];
    __shared__ int sIsLast;
    const int tid = threadIdx.x;
    const int lane = tid & 31, wid = tid >> 5;
    if (tid < 41) p[tid] = g_params[tid];
    __syncthreads();

    const int i4 = blockIdx.x * 256 + tid;      // float4 index; NS/4 = 100000 exact
    float esum = 0.0f;
    if (i4 < NS / 4) {
        const float4 z0 = ((const float4*)g_z)[i4];
        const float4 z1 = ((const float4*)(g_z + NS))[i4];
        const float4 z2 = ((const float4*)(g_z + 2 * NS))[i4];
        const float a0[4] = {z0.x, z0.y, z0.z, z0.w};
        const float a1[4] = {z1.x, z1.y, z1.z, z1.w};
        const float a2[4] = {z2.x, z2.y, z2.z, z2.w};
        float e4[4];
#pragma unroll
        for (int s = 0; s < 4; s++) {
            float e = 0.0f;
#pragma unroll
            for (int k = 0; k < 4; k++) {
                const float* P = p + k * 10;
                float v0 = a0[s] - P[0], v1 = a1[s] - P[1], v2 = a2[s] - P[2];
                float q = v0 * v0 * P[3] + v1 * v1 * P[6] + v2 * v2 * P[8]
                        + 2.0f * (v0 * v1 * P[4] + v0 * v2 * P[5] + v1 * v2 * P[7]);
                e += 0.5f * q - P[9];
            }
            e4[s] = e;
            esum += e;
        }
        float4 ov; ov.x = e4[0]; ov.y = e4[1]; ov.z = e4[2]; ov.w = e4[3];
        ((float4*)out)[i4] = ov;
    }

    float s = warp_sum(esum);
    if (lane == 0) sw[wid] = s;
    __syncthreads();
    if (tid == 0) {
        float t = 0.0f;
#pragma unroll
        for (int w = 0; w < 8; w++) t += sw[w];
        g_esum[blockIdx.x] = t;
    }
    __threadfence();
    __syncthreads();
    if (tid == 0) sIsLast = (atomicAdd(&g_cnt3, 1) == NB3 - 1);
    __syncthreads();
    if (!sIsLast) return;
    __threadfence();
    if (wid == 0) {
        double a = 0.0;
        for (int b = lane; b < NB3; b += 32) a += (double)g_esum[b];
        a = warp_dsum(a);
        if (lane == 0) {
            if (out_size > NS)
                out[NS] = p[40] + (float)(0.01 * (a / (double)NS));
            __threadfence();
            g_cnt3 = 0;             // self-reset for next graph replay
        }
    }
}

extern "C" void kernel_launch(void* const* d_in, const int* in_sizes, int n_in,
                              void* d_out, int out_size) {
    const float* x1  = (const float*)d_in[0];
    const float* ew1 = (const float*)d_in[1];
    const float* eb1 = (const float*)d_in[2];
    const float* ew2 = (const float*)d_in[3];
    const float* eb2 = (const float*)d_in[4];
    const float* ew3 = (const float*)d_in[5];
    const float* eb3 = (const float*)d_in[6];
    const float* dw1 = (const float*)d_in[7];
    const float* db1 = (const float*)d_in[8];
    const float* dw2 = (const float*)d_in[9];
    const float* db2 = (const float*)d_in[10];
    const float* dw3 = (const float*)d_in[11];
    const float* db3 = (const float*)d_in[12];
    const float* tw1 = (const float*)d_in[13];
    const float* tb1 = (const float*)d_in[14];
    const float* tw2 = (const float*)d_in[15];
    const float* tb2 = (const float*)d_in[16];
    float* out = (float*)d_out;

    k0<<<1, 256>>>(dw3, db3);
    kA<<<NBA, NTHR>>>(x1, ew1, dw3, db3);
    kB<<<NBB, NTHR>>>(eb1, ew2, eb2, ew3, eb3,
                      dw1, db1, dw2, db2,
                      tw1, tb1, tw2, tb2);
    k3<<<NB3, 256>>>(out, out_size);
}

// round 11
// speedup vs baseline: 2.1773x; 1.0978x over previous
#include <cuda_runtime.h>
#include <cstdint>
#include <math.h>

#define NS    400000
#define NTHR  256
#define NBA   1563                // kA blocks: 1563*256 = 400128 samples
#define NBB   1563                // kB blocks
#define NB3   391                 // k3 blocks (4 samples/thread)
#define NQ    41                  // 1 (loss1) + 4*10 GMM stats

// ---------------- device scratch (no allocations allowed) ----------------
__device__ float4 g_mid4[8 * NS];       // [q][n]: q=0..3 enc16, q=4..7 t16
__device__ float2 g_misc[NS];           // (n1sq, x.b3)
__device__ float  g_M[256];             // dec_w3 @ dec_w3^T
__device__ float  g_V[16];              // dec_w3 @ dec_b3
__device__ float  g_BB[1];              // ||dec_b3||^2
__device__ float  g_scratch[NBB * 48];  // per-block stat partials
__device__ float  g_z[3 * NS];          // z components, SoA
__device__ float  g_params[48];         // per-k params + loss partial
__device__ float  g_esum[NB3];          // per-block energy partials
__device__ int    g_cntB = 0;           // last-block ticket for kB (self-resetting)
__device__ int    g_cnt3 = 0;           // last-block ticket for k3

typedef unsigned long long ull;

// ---------------- helpers ----------------
__device__ __forceinline__ ull pk2(float a, float b) {
    ull r; asm("mov.b64 %0, {%1, %2};" : "=l"(r) : "f"(a), "f"(b)); return r;
}
__device__ __forceinline__ void upk(ull v, float& a, float& b) {
    asm("mov.b64 {%0, %1}, %2;" : "=f"(a), "=f"(b) : "l"(v));
}
__device__ __forceinline__ void ffma2(ull& d, ull a, ull b) {
    asm("fma.rn.f32x2 %0, %1, %2, %0;" : "+l"(d) : "l"(a), "l"(b));
}
__device__ __forceinline__ float tanh_fast(float x) {
    float e = __expf(2.0f * x);
    return 1.0f - __fdividef(2.0f, e + 1.0f);
}
__device__ __forceinline__ float warp_sum(float v) {
#pragma unroll
    for (int o = 16; o > 0; o >>= 1) v += __shfl_down_sync(0xffffffffu, v, o);
    return v;
}
__device__ __forceinline__ double warp_dsum(double v) {
#pragma unroll
    for (int o = 16; o > 0; o >>= 1) v += __shfl_down_sync(0xffffffffu, v, o);
    return v;
}

// bf16 split helpers: xh = top-16-bit truncation (exact bf16), xl = x - xh (exact f32)
__device__ __forceinline__ float hi32(float f) {
    return __uint_as_float(__float_as_uint(f) & 0xffff0000u);
}
// pack {lo: hi16(x0), hi: hi16(x1)} in one PRMT
__device__ __forceinline__ unsigned prmt7632(float x0, float x1) {
    unsigned d;
    asm("prmt.b32 %0, %1, %2, 0x7632;"
        : "=r"(d) : "r"(__float_as_uint(x0)), "r"(__float_as_uint(x1)));
    return d;
}
// pack {lo: bf16(lo), hi: bf16(hi)} (cvt: first src -> high half)
__device__ __forceinline__ unsigned bf2pack(float lo, float hi) {
    unsigned d;
    asm("cvt.rn.bf16x2.f32 %0, %1, %2;" : "=r"(d) : "f"(hi), "f"(lo));
    return d;
}
// m16n8k16 bf16 mma, f32 accumulate
__device__ __forceinline__ void mma16816(float c[4], const unsigned a[4],
                                         unsigned b0, unsigned b1) {
    asm("mma.sync.aligned.m16n8k16.row.col.f32.bf16.bf16.f32 "
        "{%0,%1,%2,%3}, {%4,%5,%6,%7}, {%8,%9}, {%0,%1,%2,%3};"
        : "+f"(c[0]), "+f"(c[1]), "+f"(c[2]), "+f"(c[3])
        : "r"(a[0]), "r"(a[1]), "r"(a[2]), "r"(a[3]), "r"(b0), "r"(b1));
}

// ---------------- K0: decoder-algebra constants (once) ----------------
__global__ void k0(const float* __restrict__ dw3, const float* __restrict__ db3) {
    __shared__ float sW[2048], sB[128];
    const int tid = threadIdx.x;   // 256
    for (int i = tid; i < 2048; i += 256) sW[i] = dw3[i];
    if (tid < 128) sB[tid] = db3[tid];
    __syncthreads();
    {
        int j = tid >> 4, l = tid & 15;
        float s = 0.0f;
#pragma unroll 8
        for (int i = 0; i < 128; i++) s += sW[j * 128 + i] * sW[l * 128 + i];
        g_M[tid] = s;
    }
    if (tid < 16) {
        float s = 0.0f;
#pragma unroll 8
        for (int i = 0; i < 128; i++) s += sW[tid * 128 + i] * sB[i];
        g_V[tid] = s;
    }
    if (tid == 16) {
        float s = 0.0f;
#pragma unroll 8
        for (int i = 0; i < 128; i++) s += sB[i] * sB[i];
        g_BB[0] = s;
    }
}

// ---------------- KA: tensor-core matvec Y[NS][33] = X @ [enc_w1 | dec_w3^T | b3] ----------------
// bf16 2-way split, all 4 cross products -> ~f32 precision. Also n1sq via f32 side-accum.
__global__ __launch_bounds__(NTHR) void kA(
    const float* __restrict__ x1,
    const float* __restrict__ ew1,
    const float* __restrict__ dw3,
    const float* __restrict__ db3)
{
    __shared__ float sWf[128 * 40];        // f32 fused W: cols 0-15 enc, 16-31 dec^T, 32 b3, 33-39 zero
    __shared__ uint4 sBf[8 * 5 * 32];      // per-thread B fragments [ks][nt][lane]: {bh0,bh1,bl0,bl1}

    const int tid = threadIdx.x;

    // stage fused W (f32)
    for (int idx = tid; idx < 5120; idx += NTHR) {
        int k = idx / 40, c = idx % 40;
        float v;
        if (c < 16)      v = ew1[k * 16 + c];
        else if (c < 32) v = dw3[(c - 16) * 128 + k];
        else if (c == 32) v = db3[k];
        else             v = 0.0f;
        sWf[idx] = v;
    }
    __syncthreads();

    // build per-thread B fragments (bf16 split): e = ks*160 + nt*32 + t
    for (int e = tid; e < 1280; e += NTHR) {
        int ks = e / 160, rem = e % 160, nt = rem / 32, t = rem % 32;
        int p = t & 3, gg = t >> 2;
        int n = nt * 8 + gg;
        int k0 = ks * 16 + 2 * p;
        float f00 = sWf[k0 * 40 + n],       f01 = sWf[(k0 + 1) * 40 + n];
        float f10 = sWf[(k0 + 8) * 40 + n], f11 = sWf[(k0 + 9) * 40 + n];
        uint4 v;
        v.x = prmt7632(f00, f01);                                 // Bh reg0 (k0, k0+1)
        v.y = prmt7632(f10, f11);                                 // Bh reg1 (k0+8, k0+9)
        v.z = bf2pack(f00 - hi32(f00), f01 - hi32(f01));          // Bl reg0
        v.w = bf2pack(f10 - hi32(f10), f11 - hi32(f11));          // Bl reg1
        sBf[e] = v;
    }
    __syncthreads();

    const int lane = tid & 31, wid = tid >> 5;
    const int g = lane >> 2, p = lane & 3;
    const int rowbase = (blockIdx.x * 8 + wid) * 32;   // 32 samples per warp

    float C[2][5][4];
#pragma unroll
    for (int m = 0; m < 2; m++)
#pragma unroll
        for (int nt = 0; nt < 5; nt++)
#pragma unroll
            for (int i = 0; i < 4; i++) C[m][nt][i] = 0.0f;
    float n1acc[4] = {0.0f, 0.0f, 0.0f, 0.0f};

#pragma unroll
    for (int ks = 0; ks < 8; ks++) {
        unsigned ah[2][4], al[2][4];
#pragma unroll
        for (int m = 0; m < 2; m++) {
#pragma unroll
            for (int sub = 0; sub < 2; sub++) {
                int r = rowbase + 16 * m + 8 * sub + g;
                if (r >= NS) r = NS - 1;
                const float* xr = x1 + (size_t)r * 128 + ks * 16 + 2 * p;
#pragma unroll
                for (int cs = 0; cs < 2; cs++) {
                    const float2 xv = *(const float2*)(xr + 8 * cs);
                    ah[m][sub + 2 * cs] = prmt7632(xv.x, xv.y);
                    al[m][sub + 2 * cs] = bf2pack(xv.x - hi32(xv.x), xv.y - hi32(xv.y));
                    n1acc[2 * m + sub] = fmaf(xv.x, xv.x,
                                          fmaf(xv.y, xv.y, n1acc[2 * m + sub]));
                }
            }
        }
#pragma unroll
        for (int nt = 0; nt < 5; nt++) {
            const uint4 B = sBf[(ks * 5 + nt) * 32 + lane];
#pragma unroll
            for (int m = 0; m < 2; m++) {
                mma16816(C[m][nt], ah[m], B.x, B.y);   // xh * Wh
                mma16816(C[m][nt], al[m], B.x, B.y);   // xl * Wh
                mma16816(C[m][nt], ah[m], B.z, B.w);   // xh * Wl
                mma16816(C[m][nt], al[m], B.z, B.w);   // xl * Wl
            }
        }
    }

    // n1sq: reduce over the 4 lanes of each quad (cols are split across p)
#pragma unroll
    for (int i = 0; i < 4; i++) {
        n1acc[i] += __shfl_xor_sync(0xffffffffu, n1acc[i], 1);
        n1acc[i] += __shfl_xor_sync(0xffffffffu, n1acc[i], 2);
    }

    // epilogue: C[m][nt][{2sub,2sub+1}] = Y[row][8nt + 2p + {0,1}]
#pragma unroll
    for (int m = 0; m < 2; m++) {
#pragma unroll
        for (int sub = 0; sub < 2; sub++) {
            const int r = rowbase + 16 * m + 8 * sub + g;
            if (r < NS) {
#pragma unroll
                for (int nt = 0; nt < 4; nt++) {
                    float2 v = make_float2(C[m][nt][2 * sub], C[m][nt][2 * sub + 1]);
                    int q = 2 * nt + (p >> 1), half = p & 1;
                    ((float2*)g_mid4)[(size_t)(q * NS + r) * 2 + half] = v;
                }
                if (p == 0)   // col 32 = x.b3 lives in quad-lane 0
                    g_misc[r] = make_float2(n1acc[2 * m + sub], C[m][4][2 * sub]);
            }
        }
    }
}

// ---------------- KB: per-sample tail + stats + (last block) GMM params ----------------
__global__ __launch_bounds__(NTHR) void kB(
    const float* __restrict__ eb1,
    const float* __restrict__ ew2, const float* __restrict__ eb2,
    const float* __restrict__ ew3, const float* __restrict__ eb3,
    const float* __restrict__ dw1, const float* __restrict__ db1,
    const float* __restrict__ dw2, const float* __restrict__ db2,
    const float* __restrict__ tw1, const float* __restrict__ tb1,
    const float* __restrict__ tw2, const float* __restrict__ tb2)
{
    __shared__ __align__(16) float sM[256];
    __shared__ float sV[16];
    __shared__ float sEB1[16], sEW2[128], sEB2[8], sEW3[8];
    __shared__ float sDW1[8], sDB1[8], sDW2[128], sDB2[16];
    __shared__ float sTW1[24], sTB1[8], sTW2[32], sTB2[4];
    __shared__ float sEB3, sBB;
    __shared__ float sWred[NQ][8];
    __shared__ double sTot[NQ];
    __shared__ double sL3[4];
    __shared__ int sIsLast;

    const int tid = threadIdx.x;
    const int lane = tid & 31, wid = tid >> 5;

    if (tid < 256) sM[tid] = g_M[tid];
    if (tid < 128) { sEW2[tid] = ew2[tid]; sDW2[tid] = dw2[tid]; }
    if (tid < 16)  { sEB1[tid] = eb1[tid]; sDB2[tid] = db2[tid]; sV[tid] = g_V[tid]; }
    if (tid < 8)   { sEB2[tid] = eb2[tid]; sEW3[tid] = ew3[tid];
                     sDW1[tid] = dw1[tid]; sDB1[tid] = db1[tid]; sTB1[tid] = tb1[tid]; }
    if (tid < 24)  sTW1[tid] = tw1[tid];
    if (tid < 32)  sTW2[tid] = tw2[tid];
    if (tid < 4)   sTB2[tid] = tb2[tid];
    if (tid == 0)  { sEB3 = eb3[0]; sBB = g_BB[0]; }
    __syncthreads();

    const int n = blockIdx.x * NTHR + tid;
    const int ns = (n < NS) ? n : (NS - 1);
    const float valid = (n < NS) ? 1.0f : 0.0f;

    float enc[16], t16[16];
#pragma unroll
    for (int q = 0; q < 4; q++) {
        const float4 e = g_mid4[q * NS + ns];
        enc[4 * q] = e.x; enc[4 * q + 1] = e.y; enc[4 * q + 2] = e.z; enc[4 * q + 3] = e.w;
        const float4 t = g_mid4[(4 + q) * NS + ns];
        t16[4 * q] = t.x; t16[4 * q + 1] = t.y; t16[4 * q + 2] = t.z; t16[4 * q + 3] = t.w;
    }
    const float2 mi = g_misc[ns];
    const float n1sq = mi.x, xb3 = mi.y;

    float h1[16];
#pragma unroll
    for (int j = 0; j < 16; j++) h1[j] = tanh_fast(enc[j] + sEB1[j]);
    float h2[8];
#pragma unroll
    for (int o = 0; o < 8; o++) {
        float sm = sEB2[o];
#pragma unroll
        for (int i = 0; i < 16; i++) sm += h1[i] * sEW2[i * 8 + o];
        h2[o] = tanh_fast(sm);
    }
    float s3 = sEB3;
#pragma unroll
    for (int i = 0; i < 8; i++) s3 += h2[i] * sEW3[i];
    const float zc0 = tanh_fast(s3);

    float g1[8];
#pragma unroll
    for (int o = 0; o < 8; o++) g1[o] = tanh_fast(sDB1[o] + zc0 * sDW1[o]);
    float g2[16];
    ull gp[8];
#pragma unroll
    for (int o = 0; o < 16; o++) {
        float sm = sDB2[o];
#pragma unroll
        for (int i = 0; i < 8; i++) sm += g1[i] * sDW2[i * 16 + o];
        g2[o] = tanh_fast(sm);
    }
#pragma unroll
    for (int q = 0; q < 8; q++) gp[q] = pk2(g2[2 * q], g2[2 * q + 1]);

    float dotv = xb3;
#pragma unroll
    for (int j = 0; j < 16; j++) dotv += g2[j] * t16[j];
    float n2sq = sBB;
#pragma unroll
    for (int j = 0; j < 16; j++) {
        ull acc = pk2(2.0f * sV[j], 0.0f);
        const ulonglong2* Mr = (const ulonglong2*)(sM + j * 16);
#pragma unroll
        for (int q = 0; q < 4; q++) {
            ulonglong2 m = Mr[q];
            ffma2(acc, gp[2 * q],     m.x);
            ffma2(acc, gp[2 * q + 1], m.y);
        }
        float pa, pb; upk(acc, pa, pb);
        n2sq += g2[j] * (pa + pb);
    }
    const float dsq = fmaxf(n1sq - 2.0f * dotv + n2sq, 0.0f);
    const float zc1 = dotv * rsqrtf(n1sq * n2sq);
    const float zc2 = sqrtf(dsq);

    if (n < NS) {
        g_z[n]          = zc0;
        g_z[NS + n]     = zc1;
        g_z[2 * NS + n] = zc2;
    }

    float gm[4];
    {
        float tt[8];
#pragma unroll
        for (int o = 0; o < 8; o++)
            tt[o] = tanh_fast(sTB1[o] + zc0 * sTW1[o] + zc1 * sTW1[8 + o] + zc2 * sTW1[16 + o]);
        float lg[4];
#pragma unroll
        for (int k = 0; k < 4; k++) {
            float sm = sTB2[k];
#pragma unroll
            for (int o = 0; o < 8; o++) sm += tt[o] * sTW2[o * 4 + k];
            lg[k] = sm;
        }
        float m = fmaxf(fmaxf(lg[0], lg[1]), fmaxf(lg[2], lg[3]));
        float e0 = __expf(lg[0] - m), e1 = __expf(lg[1] - m);
        float e2 = __expf(lg[2] - m), e3 = __expf(lg[3] - m);
        float inv = __fdividef(1.0f, e0 + e1 + e2 + e3) * valid;
        gm[0] = e0 * inv; gm[1] = e1 * inv; gm[2] = e2 * inv; gm[3] = e3 * inv;
    }
    const float dsv = dsq * valid;
    const float f[3] = {zc0, zc1, zc2};

    {
        float s = warp_sum(dsv);
        if (lane == 0) sWred[0][wid] = s;
    }
#pragma unroll
    for (int k = 0; k < 4; k++) {
        float vv[10];
        vv[0] = gm[k];
#pragma unroll
        for (int d = 0; d < 3; d++) vv[1 + d] = gm[k] * f[d];
        int c = 4;
#pragma unroll
        for (int d = 0; d < 3; d++)
#pragma unroll
            for (int e = d; e < 3; e++) vv[c++] = gm[k] * f[d] * f[e];
#pragma unroll
        for (int q = 0; q < 10; q++) {
            float s = warp_sum(vv[q]);
            if (lane == 0) sWred[1 + k * 10 + q][wid] = s;
        }
    }
    __syncthreads();
    if (tid < NQ) {
        float s = 0.0f;
#pragma unroll
        for (int w = 0; w < 8; w++) s += sWred[tid][w];
        g_scratch[blockIdx.x * 48 + tid] = s;
    }

    __threadfence();
    __syncthreads();
    if (tid == 0) sIsLast = (atomicAdd(&g_cntB, 1) == NBB - 1);
    __syncthreads();
    if (!sIsLast) return;
    __threadfence();

    for (int q = wid; q < NQ; q += 8) {
        double s = 0.0;
        for (int b = lane; b < NBB; b += 32) s += (double)g_scratch[b * 48 + q];
        s = warp_dsum(s);
        if (lane == 0) sTot[q] = s;
    }
    __syncthreads();
    if (tid < 4) {
        const int k = tid;
        const double* T = sTot + 1 + k * 10;
        double S0 = T[0];
        double m0 = T[1] / S0, m1 = T[2] / S0, m2 = T[3] / S0;
        double s00 = T[4] / S0 - m0 * m0, s01 = T[5] / S0 - m0 * m1, s02 = T[6] / S0 - m0 * m2;
        double s11 = T[7] / S0 - m1 * m1, s12 = T[8] / S0 - m1 * m2, s22 = T[9] / S0 - m2 * m2;
        double c00 = s11 * s22 - s12 * s12;
        double c01 = s02 * s12 - s01 * s22;
        double c02 = s01 * s12 - s02 * s11;
        double det = s00 * c00 + s01 * c01 + s02 * c02;
        double inv = 1.0 / det;
        double phi = S0 / (double)NS;
        double ck = log(phi) - 0.5 * (3.0 * log(2.0 * M_PI) + log(det));
        g_params[k * 10 + 0] = (float)m0;
        g_params[k * 10 + 1] = (float)m1;
        g_params[k * 10 + 2] = (float)m2;
        g_params[k * 10 + 3] = (float)(c00 * inv);
        g_params[k * 10 + 4] = (float)(c01 * inv);
        g_params[k * 10 + 5] = (float)(c02 * inv);
        g_params[k * 10 + 6] = (float)((s00 * s22 - s02 * s02) * inv);
        g_params[k * 10 + 7] = (float)((s02 * s01 - s00 * s12) * inv);
        g_params[k * 10 + 8] = (float)((s00 * s11 - s01 * s01) * inv);
        g_params[k * 10 + 9] = (float)ck;
        sL3[k] = 1.0 / s00 + 1.0 / s11 + 1.0 / s22;
    }
    __syncthreads();
    if (tid == 0) {
        double loss1 = sTot[0] / (double)NS;
        g_params[40] = (float)(loss1 + 1e-4 * (sL3[0] + sL3[1] + sL3[2] + sL3[3]));
        __threadfence();
        g_cntB = 0;                 // self-reset for next graph replay
    }
}

// ---------------- K3: energy, 4 samples/thread + (last block) final loss ----------------
__global__ __launch_bounds__(256) void k3(float* __restrict__ out, int out_size) {
    __shared__ float p[48];
    __shared__ float sw[8];
    __shared__ int sIsLast;
    const int tid = threadIdx.x;
    const int lane = tid & 31, wid = tid >> 5;
    if (tid < 41) p[tid] = g_params[tid];
    __syncthreads();

    const int i4 = blockIdx.x * 256 + tid;      // float4 index; NS/4 = 100000 exact
    float esum = 0.0f;
    if (i4 < NS / 4) {
        const float4 z0 = ((const float4*)g_z)[i4];
        const float4 z1 = ((const float4*)(g_z + NS))[i4];
        const float4 z2 = ((const float4*)(g_z + 2 * NS))[i4];
        const float a0[4] = {z0.x, z0.y, z0.z, z0.w};
        const float a1[4] = {z1.x, z1.y, z1.z, z1.w};
        const float a2[4] = {z2.x, z2.y, z2.z, z2.w};
        float e4[4];
#pragma unroll
        for (int s = 0; s < 4; s++) {
            float e = 0.0f;
#pragma unroll
            for (int k = 0; k < 4; k++) {
                const float* P = p + k * 10;
                float v0 = a0[s] - P[0], v1 = a1[s] - P[1], v2 = a2[s] - P[2];
                float q = v0 * v0 * P[3] + v1 * v1 * P[6] + v2 * v2 * P[8]
                        + 2.0f * (v0 * v1 * P[4] + v0 * v2 * P[5] + v1 * v2 * P[7]);
                e += 0.5f * q - P[9];
            }
            e4[s] = e;
            esum += e;
        }
        float4 ov; ov.x = e4[0]; ov.y = e4[1]; ov.z = e4[2]; ov.w = e4[3];
        ((float4*)out)[i4] = ov;
    }

    float s = warp_sum(esum);
    if (lane == 0) sw[wid] = s;
    __syncthreads();
    if (tid == 0) {
        float t = 0.0f;
#pragma unroll
        for (int w = 0; w < 8; w++) t += sw[w];
        g_esum[blockIdx.x] = t;
    }
    __threadfence();
    __syncthreads();
    if (tid == 0) sIsLast = (atomicAdd(&g_cnt3, 1) == NB3 - 1);
    __syncthreads();
    if (!sIsLast) return;
    __threadfence();
    if (wid == 0) {
        double a = 0.0;
        for (int b = lane; b < NB3; b += 32) a += (double)g_esum[b];
        a = warp_dsum(a);
        if (lane == 0) {
            if (out_size > NS)
                out[NS] = p[40] + (float)(0.01 * (a / (double)NS));
            __threadfence();
            g_cnt3 = 0;             // self-reset for next graph replay
        }
    }
}

extern "C" void kernel_launch(void* const* d_in, const int* in_sizes, int n_in,
                              void* d_out, int out_size) {
    const float* x1  = (const float*)d_in[0];
    const float* ew1 = (const float*)d_in[1];
    const float* eb1 = (const float*)d_in[2];
    const float* ew2 = (const float*)d_in[3];
    const float* eb2 = (const float*)d_in[4];
    const float* ew3 = (const float*)d_in[5];
    const float* eb3 = (const float*)d_in[6];
    const float* dw1 = (const float*)d_in[7];
    const float* db1 = (const float*)d_in[8];
    const float* dw2 = (const float*)d_in[9];
    const float* db2 = (const float*)d_in[10];
    const float* dw3 = (const float*)d_in[11];
    const float* db3 = (const float*)d_in[12];
    const float* tw1 = (const float*)d_in[13];
    const float* tb1 = (const float*)d_in[14];
    const float* tw2 = (const float*)d_in[15];
    const float* tb2 = (const float*)d_in[16];
    float* out = (float*)d_out;

    k0<<<1, 256>>>(dw3, db3);
    kA<<<NBA, NTHR>>>(x1, ew1, dw3, db3);
    kB<<<NBB, NTHR>>>(eb1, ew2, eb2, ew3, eb3,
                      dw1, db1, dw2, db2,
                      tw1, tb1, tw2, tb2);
    k3<<<NB3, 256>>>(out, out_size);
}